// round 10
// baseline (speedup 1.0000x reference)
#include <cuda_runtime.h>
#include <cuda_bf16.h>
#include <cstdint>

// ---------------------------------------------------------------------------
// Problem constants
// ---------------------------------------------------------------------------
constexpr int BSZ  = 8;
constexpr int NCTX = 4096;
constexpr int MCTX = 300;
constexpr int DM   = 1152;
constexpr int NH   = 16;
constexpr int HD   = 72;           // DM / NH
constexpr int MP   = 320;          // padded M for K^T / V scratch

// ---------------------------------------------------------------------------
// Scratch (device globals; zero-initialized, no allocations allowed)
// ---------------------------------------------------------------------------
__device__ float g_q   [(size_t)BSZ * NCTX * DM];          // [B,N,DM]
__device__ float g_attn[(size_t)BSZ * NCTX * DM];          // [B,N,DM]
__device__ float g_kT  [(size_t)BSZ * NH * HD * MP];       // [B,H,D,Mpad] (pads stay 0)
__device__ float g_v2  [(size_t)BSZ * NH * MP * 80];       // [B,H,Mpad,80] (pads stay 0)

// ---------------------------------------------------------------------------
// Helpers
// ---------------------------------------------------------------------------
__device__ __forceinline__ uint32_t smem_u32(const void* p) {
    uint32_t a;
    asm("{ .reg .u64 t; cvta.to.shared.u64 t, %1; cvt.u32.u64 %0, t; }"
        : "=r"(a) : "l"(p));
    return a;
}

__device__ __forceinline__ uint32_t pack_bf2(__nv_bfloat16 a, __nv_bfloat16 b) {
    __nv_bfloat162 t(a, b);
    return *reinterpret_cast<uint32_t*>(&t);
}

__device__ __forceinline__ void split_bf16(float v, __nv_bfloat16& h, __nv_bfloat16& l) {
    h = __float2bfloat16_rn(v);
    l = __float2bfloat16_rn(v - __bfloat162float(h));
}

__device__ __forceinline__ void ldsm_x4(uint32_t& r0, uint32_t& r1,
                                        uint32_t& r2, uint32_t& r3, uint32_t a) {
    asm volatile("ldmatrix.sync.aligned.m8n8.x4.shared.b16 {%0,%1,%2,%3}, [%4];"
                 : "=r"(r0), "=r"(r1), "=r"(r2), "=r"(r3) : "r"(a));
}

__device__ __forceinline__ void ldsm_x4_t(uint32_t& r0, uint32_t& r1,
                                          uint32_t& r2, uint32_t& r3, uint32_t a) {
    asm volatile("ldmatrix.sync.aligned.m8n8.x4.trans.shared.b16 {%0,%1,%2,%3}, [%4];"
                 : "=r"(r0), "=r"(r1), "=r"(r2), "=r"(r3) : "r"(a));
}

__device__ __forceinline__ void mma16816(float* d, const uint32_t* a,
                                         uint32_t b0, uint32_t b1) {
    asm volatile(
        "mma.sync.aligned.m16n8k16.row.col.f32.bf16.bf16.f32 "
        "{%0,%1,%2,%3}, {%4,%5,%6,%7}, {%8,%9}, {%0,%1,%2,%3};"
        : "+f"(d[0]), "+f"(d[1]), "+f"(d[2]), "+f"(d[3])
        : "r"(a[0]), "r"(a[1]), "r"(a[2]), "r"(a[3]), "r"(b0), "r"(b1));
}

// ---------------------------------------------------------------------------
// HMMA split-bf16 GEMM: C[Mr,Nc] = A[Mr,Kd] @ B[Kd,Nc] + bias
// CTA tile 256x128, BK=32, 8 warps (4x2 of 64x64), 256 threads.
// MODE 0: row-major store. MODE 1: KV scatter into g_kT / g_v2.
// ---------------------------------------------------------------------------
constexpr int AS_STRIDE = 40;    // 32 + 8 pad (elems)
constexpr int BS_STRIDE = 136;   // 128 + 8 pad (elems)
constexpr int A_TILE_B  = 256 * AS_STRIDE * 2;   // 20480
constexpr int B_TILE_B  = 32  * BS_STRIDE * 2;   // 8704
constexpr int OFF_AH = 0;
constexpr int OFF_AL = OFF_AH + A_TILE_B;        // 20480
constexpr int OFF_BH = OFF_AL + A_TILE_B;        // 40960
constexpr int OFF_BL = OFF_BH + B_TILE_B;        // 49664
constexpr int GEMM_SMEM = OFF_BL + B_TILE_B;     // 58368

template <int MODE>
__global__ __launch_bounds__(256, 1)
void gemm_hmma(const float* __restrict__ A, const float* __restrict__ Bm,
               const float* __restrict__ bias, float* __restrict__ C,
               int Mr, int Nc, int Kd)
{
    extern __shared__ char dsm[];
    const uint32_t sbase = smem_u32(dsm);

    const int tid  = threadIdx.x;
    const int wid  = tid >> 5;
    const int lane = tid & 31;
    const int n0   = blockIdx.x * 128;
    const int m0   = blockIdx.y * 256;
    const int wm   = wid >> 1;          // 0..3
    const int wn   = wid & 1;           // 0..1

    // producer mappings (coalesced)
    const int arBase = tid >> 3;        // A: 32 rows per pass, 8 passes
    const int acol   = (tid & 7) * 4;
    const int brow   = tid >> 5;        // B: 8 rows per pass, 4 passes
    const int bcol   = (tid & 31) * 4;

    // consumer lane addressing
    const int aFragRow = wm * 64 + (lane & 15);
    const int aFragCol = (lane >> 4) * 8;
    const int bFragRow = lane & 15;
    const int bFragCol = wn * 64 + (lane >> 4) * 8;

    float acc[4][8][4];
    #pragma unroll
    for (int i = 0; i < 4; i++)
        #pragma unroll
        for (int j = 0; j < 8; j++)
            #pragma unroll
            for (int e = 0; e < 4; e++) acc[i][j][e] = 0.0f;

    const int nchunks = Kd / 32;

    for (int c = 0; c < nchunks; ++c) {
        const int k0 = c * 32;

        // ---- produce A tile (256x32) hi/lo ----
        {
            char* pAH = dsm + OFF_AH;
            char* pAL = dsm + OFF_AL;
            #pragma unroll
            for (int it = 0; it < 8; ++it) {
                const int r = arBase + it * 32;
                int arow = m0 + r; if (arow >= Mr) arow = Mr - 1;
                float4 v = *(const float4*)(A + (size_t)arow * Kd + k0 + acol);
                __nv_bfloat16 h0, h1, h2, h3, l0, l1, l2, l3;
                split_bf16(v.x, h0, l0); split_bf16(v.y, h1, l1);
                split_bf16(v.z, h2, l2); split_bf16(v.w, h3, l3);
                const uint32_t off = (uint32_t)(r * AS_STRIDE + acol) * 2;
                *(uint2*)(pAH + off) = make_uint2(pack_bf2(h0, h1), pack_bf2(h2, h3));
                *(uint2*)(pAL + off) = make_uint2(pack_bf2(l0, l1), pack_bf2(l2, l3));
            }
        }
        // ---- produce B tile (32x128) hi/lo ----
        {
            char* pBH = dsm + OFF_BH;
            char* pBL = dsm + OFF_BL;
            #pragma unroll
            for (int it = 0; it < 4; ++it) {
                const int r = brow + it * 8;
                float4 v = *(const float4*)(Bm + (size_t)(k0 + r) * Nc + n0 + bcol);
                __nv_bfloat16 h0, h1, h2, h3, l0, l1, l2, l3;
                split_bf16(v.x, h0, l0); split_bf16(v.y, h1, l1);
                split_bf16(v.z, h2, l2); split_bf16(v.w, h3, l3);
                const uint32_t off = (uint32_t)(r * BS_STRIDE + bcol) * 2;
                *(uint2*)(pBH + off) = make_uint2(pack_bf2(h0, h1), pack_bf2(h2, h3));
                *(uint2*)(pBL + off) = make_uint2(pack_bf2(l0, l1), pack_bf2(l2, l3));
            }
        }
        __syncthreads();

        const uint32_t sAH = sbase + OFF_AH;
        const uint32_t sAL = sbase + OFF_AL;
        const uint32_t sBH = sbase + OFF_BH;
        const uint32_t sBL = sbase + OFF_BL;

        #pragma unroll
        for (int kk = 0; kk < 32; kk += 16) {
            uint32_t Ah[4][4], Bh[4][4], Bl[4][4];
            #pragma unroll
            for (int mi = 0; mi < 4; ++mi) {
                uint32_t a = sAH + (uint32_t)((aFragRow + mi * 16) * AS_STRIDE
                                              + kk + aFragCol) * 2;
                ldsm_x4(Ah[mi][0], Ah[mi][1], Ah[mi][2], Ah[mi][3], a);
            }
            #pragma unroll
            for (int nj = 0; nj < 4; ++nj) {
                uint32_t boff = (uint32_t)((kk + bFragRow) * BS_STRIDE
                                           + bFragCol + nj * 16) * 2;
                ldsm_x4_t(Bh[nj][0], Bh[nj][1], Bh[nj][2], Bh[nj][3], sBH + boff);
                ldsm_x4_t(Bl[nj][0], Bl[nj][1], Bl[nj][2], Bl[nj][3], sBL + boff);
            }
            #pragma unroll
            for (int mi = 0; mi < 4; ++mi)
                #pragma unroll
                for (int nf = 0; nf < 8; ++nf) {
                    const int nj = nf >> 1, sub = (nf & 1) * 2;
                    mma16816(acc[mi][nf], Ah[mi], Bh[nj][sub], Bh[nj][sub + 1]);
                    mma16816(acc[mi][nf], Ah[mi], Bl[nj][sub], Bl[nj][sub + 1]);
                }
            uint32_t Al[4][4];
            #pragma unroll
            for (int mi = 0; mi < 4; ++mi) {
                uint32_t a = sAL + (uint32_t)((aFragRow + mi * 16) * AS_STRIDE
                                              + kk + aFragCol) * 2;
                ldsm_x4(Al[mi][0], Al[mi][1], Al[mi][2], Al[mi][3], a);
            }
            #pragma unroll
            for (int mi = 0; mi < 4; ++mi)
                #pragma unroll
                for (int nf = 0; nf < 8; ++nf) {
                    const int nj = nf >> 1, sub = (nf & 1) * 2;
                    mma16816(acc[mi][nf], Al[mi], Bh[nj][sub], Bh[nj][sub + 1]);
                }
        }
        __syncthreads();
    }

    // ---------------- epilogue ----------------
    const int g = lane >> 2;
    const int t = lane & 3;
    #pragma unroll
    for (int mi = 0; mi < 4; ++mi) {
        #pragma unroll
        for (int half = 0; half < 2; ++half) {
            const int row = m0 + wm * 64 + mi * 16 + g + half * 8;
            if (row >= Mr) continue;
            #pragma unroll
            for (int nf = 0; nf < 8; ++nf) {
                const int col = n0 + wn * 64 + nf * 8 + 2 * t;
                float v0 = acc[mi][nf][half * 2 + 0] + bias[col];
                float v1 = acc[mi][nf][half * 2 + 1] + bias[col + 1];
                if (MODE == 0) {
                    *(float2*)(C + (size_t)row * Nc + col) = make_float2(v0, v1);
                } else {
                    const int b = row / MCTX, m = row - b * MCTX;
                    #pragma unroll
                    for (int e = 0; e < 2; ++e) {
                        int c2 = col + e;
                        const float val = e ? v1 : v0;
                        if (c2 < DM) {   // K: transposed [b,h,d,m]
                            const int h = c2 / HD, d = c2 - h * HD;
                            g_kT[((size_t)(b * NH + h) * HD + d) * MP + m] = val;
                        } else {         // V: [b,h,m,80]
                            c2 -= DM;
                            const int h = c2 / HD, d = c2 - h * HD;
                            g_v2[((size_t)(b * NH + h) * MP + m) * 80 + d] = val;
                        }
                    }
                }
            }
        }
    }
}

// ---------------------------------------------------------------------------
// Tensor-core attention (flash-style, no max subtraction — scores are O(1)).
// CTA = (b, h, 128 q-rows); 4 warps x 32 q-rows; stream M in chunks of 64.
// Split-3 bf16 on both QK^T and P@V; O and row-sums accumulate un-rescaled.
// ---------------------------------------------------------------------------
constexpr int QR   = 128;
constexpr int MC   = 64;
constexpr int DP   = 80;    // padded head dim
constexpr int QSTR = 88;    // smem strides (elems), 16B-aligned rows
constexpr int KSTR = 72;
constexpr int VSTR = 88;
constexpr int OQH = 0;
constexpr int OQL = OQH + QR * QSTR * 2;     // 22528
constexpr int OKH = OQL + QR * QSTR * 2;     // 45056
constexpr int OKL = OKH + DP * KSTR * 2;     // 56576
constexpr int OVH = OKL + DP * KSTR * 2;     // 68096
constexpr int OVL = OVH + MC * VSTR * 2;     // 79360
constexpr int ATTN_SMEM = OVL + MC * VSTR * 2; // 90624

__global__ __launch_bounds__(128, 2)
void attn_tc(const int* __restrict__ mask, float* __restrict__ attn_out)
{
    extern __shared__ char dsm[];
    const uint32_t sbase = smem_u32(dsm);

    const int b   = blockIdx.z;
    const int h   = blockIdx.y;
    const int q0  = blockIdx.x * QR;
    const int tid = threadIdx.x;
    const int wid = tid >> 5;
    const int lane = tid & 31;
    const int g   = lane >> 2;
    const int t   = lane & 3;
    const int wq0 = wid * 32;
    const int mv  = mask[b];

    const float scale = rsqrtf((float)HD);

    // ---- produce Q tile (128 x 80; cols 72..79 zero), scale folded in ----
    {
        char* pQH = dsm + OQH;
        char* pQL = dsm + OQL;
        const float* qg = g_q + ((size_t)(b * NCTX) + q0) * DM + h * HD;
        for (int task = tid; task < QR * 18; task += 128) {
            const int r = task / 18, f4 = task - r * 18;
            float4 v = *(const float4*)(qg + (size_t)r * DM + f4 * 4);
            v.x *= scale; v.y *= scale; v.z *= scale; v.w *= scale;
            __nv_bfloat16 h0, h1, h2, h3, l0, l1, l2, l3;
            split_bf16(v.x, h0, l0); split_bf16(v.y, h1, l1);
            split_bf16(v.z, h2, l2); split_bf16(v.w, h3, l3);
            const uint32_t off = (uint32_t)(r * QSTR + f4 * 4) * 2;
            *(uint2*)(pQH + off) = make_uint2(pack_bf2(h0, h1), pack_bf2(h2, h3));
            *(uint2*)(pQL + off) = make_uint2(pack_bf2(l0, l1), pack_bf2(l2, l3));
        }
        for (int task = tid; task < QR * 2; task += 128) {
            const int r = task >> 1, f4 = 18 + (task & 1);
            const uint32_t off = (uint32_t)(r * QSTR + f4 * 4) * 2;
            *(uint2*)(pQH + off) = make_uint2(0u, 0u);
            *(uint2*)(pQL + off) = make_uint2(0u, 0u);
        }
    }

    float o[2][10][4];
    #pragma unroll
    for (int i = 0; i < 2; i++)
        #pragma unroll
        for (int j = 0; j < 10; j++)
            #pragma unroll
            for (int e = 0; e < 4; e++) o[i][j][e] = 0.0f;
    float rs[4] = {0.f, 0.f, 0.f, 0.f};

    for (int c0 = 0; c0 < mv; c0 += MC) {
        // ---- produce K^T tile (80 d-rows x 64 m-cols; rows 72..79 zero) ----
        {
            char* pKH = dsm + OKH;
            char* pKL = dsm + OKL;
            const float* kg = g_kT + (size_t)(b * NH + h) * HD * MP + c0;
            for (int task = tid; task < HD * 16; task += 128) {
                const int d = task >> 4, f4 = task & 15;
                float4 v = *(const float4*)(kg + (size_t)d * MP + f4 * 4);
                __nv_bfloat16 h0, h1, h2, h3, l0, l1, l2, l3;
                split_bf16(v.x, h0, l0); split_bf16(v.y, h1, l1);
                split_bf16(v.z, h2, l2); split_bf16(v.w, h3, l3);
                const uint32_t off = (uint32_t)(d * KSTR + f4 * 4) * 2;
                *(uint2*)(pKH + off) = make_uint2(pack_bf2(h0, h1), pack_bf2(h2, h3));
                *(uint2*)(pKL + off) = make_uint2(pack_bf2(l0, l1), pack_bf2(l2, l3));
            }
            for (int task = tid; task < 8 * 16; task += 128) {
                const int d = HD + (task >> 4), f4 = task & 15;
                const uint32_t off = (uint32_t)(d * KSTR + f4 * 4) * 2;
                *(uint2*)(pKH + off) = make_uint2(0u, 0u);
                *(uint2*)(pKL + off) = make_uint2(0u, 0u);
            }
        }
        // ---- produce V tile (64 m-rows x 80 d-cols) ----
        {
            char* pVH = dsm + OVH;
            char* pVL = dsm + OVL;
            const float* vg = g_v2 + ((size_t)(b * NH + h) * MP + c0) * 80;
            for (int task = tid; task < MC * 20; task += 128) {
                const int m = task / 20, f4 = task - m * 20;
                float4 v = *(const float4*)(vg + (size_t)m * 80 + f4 * 4);
                __nv_bfloat16 h0, h1, h2, h3, l0, l1, l2, l3;
                split_bf16(v.x, h0, l0); split_bf16(v.y, h1, l1);
                split_bf16(v.z, h2, l2); split_bf16(v.w, h3, l3);
                const uint32_t off = (uint32_t)(m * VSTR + f4 * 4) * 2;
                *(uint2*)(pVH + off) = make_uint2(pack_bf2(h0, h1), pack_bf2(h2, h3));
                *(uint2*)(pVL + off) = make_uint2(pack_bf2(l0, l1), pack_bf2(l2, l3));
            }
        }
        __syncthreads();

        // ---- S = Q @ K^T (split-3) ----
        float S[2][8][4];
        #pragma unroll
        for (int i = 0; i < 2; i++)
            #pragma unroll
            for (int j = 0; j < 8; j++)
                #pragma unroll
                for (int e = 0; e < 4; e++) S[i][j][e] = 0.0f;

        #pragma unroll
        for (int kk = 0; kk < 5; ++kk) {
            uint32_t Ah[2][4], Al[2][4];
            #pragma unroll
            for (int mi = 0; mi < 2; ++mi) {
                const uint32_t aoff =
                    (uint32_t)((wq0 + mi * 16 + (lane & 15)) * QSTR
                               + kk * 16 + (lane >> 4) * 8) * 2;
                ldsm_x4(Ah[mi][0], Ah[mi][1], Ah[mi][2], Ah[mi][3], sbase + OQH + aoff);
                ldsm_x4(Al[mi][0], Al[mi][1], Al[mi][2], Al[mi][3], sbase + OQL + aoff);
            }
            #pragma unroll
            for (int nj = 0; nj < 4; ++nj) {
                uint32_t Bh[4], Bl[4];
                const uint32_t boff =
                    (uint32_t)((kk * 16 + (lane & 15)) * KSTR
                               + nj * 16 + (lane >> 4) * 8) * 2;
                ldsm_x4_t(Bh[0], Bh[1], Bh[2], Bh[3], sbase + OKH + boff);
                ldsm_x4_t(Bl[0], Bl[1], Bl[2], Bl[3], sbase + OKL + boff);
                #pragma unroll
                for (int mi = 0; mi < 2; ++mi) {
                    mma16816(S[mi][2 * nj + 0], Ah[mi], Bh[0], Bh[1]);
                    mma16816(S[mi][2 * nj + 1], Ah[mi], Bh[2], Bh[3]);
                    mma16816(S[mi][2 * nj + 0], Ah[mi], Bl[0], Bl[1]);
                    mma16816(S[mi][2 * nj + 1], Ah[mi], Bl[2], Bl[3]);
                    mma16816(S[mi][2 * nj + 0], Al[mi], Bh[0], Bh[1]);
                    mma16816(S[mi][2 * nj + 1], Al[mi], Bh[2], Bh[3]);
                }
            }
        }

        // ---- softmax numerators p = exp(s), masked; accumulate row sums ----
        #pragma unroll
        for (int mi = 0; mi < 2; ++mi)
            #pragma unroll
            for (int nf = 0; nf < 8; ++nf)
                #pragma unroll
                for (int e = 0; e < 4; ++e) {
                    const int col = c0 + nf * 8 + 2 * t + (e & 1);
                    const float p = (col < mv) ? __expf(S[mi][nf][e]) : 0.0f;
                    S[mi][nf][e] = p;
                    rs[mi * 2 + (e >> 1)] += p;
                }

        // ---- O += P @ V (split-3) ----
        #pragma unroll
        for (int kk2 = 0; kk2 < 4; ++kk2) {
            uint32_t Ph[2][4], Pl[2][4];
            #pragma unroll
            for (int mi = 0; mi < 2; ++mi) {
                const int nfa = 2 * kk2, nfb = nfa + 1;
                __nv_bfloat16 hh, ll;
                uint32_t hp[8], lp[8];
                #pragma unroll
                for (int e = 0; e < 4; ++e) {
                    split_bf16(S[mi][nfa][e], hh, ll);
                    hp[e] = (uint32_t)*(uint16_t*)&hh;
                    lp[e] = (uint32_t)*(uint16_t*)&ll;
                    split_bf16(S[mi][nfb][e], hh, ll);
                    hp[4 + e] = (uint32_t)*(uint16_t*)&hh;
                    lp[4 + e] = (uint32_t)*(uint16_t*)&ll;
                }
                Ph[mi][0] = hp[0] | (hp[1] << 16);
                Ph[mi][1] = hp[2] | (hp[3] << 16);
                Ph[mi][2] = hp[4] | (hp[5] << 16);
                Ph[mi][3] = hp[6] | (hp[7] << 16);
                Pl[mi][0] = lp[0] | (lp[1] << 16);
                Pl[mi][1] = lp[2] | (lp[3] << 16);
                Pl[mi][2] = lp[4] | (lp[5] << 16);
                Pl[mi][3] = lp[6] | (lp[7] << 16);
            }
            #pragma unroll
            for (int vt = 0; vt < 5; ++vt) {
                uint32_t Vh[4], Vl[4];
                const uint32_t voff =
                    (uint32_t)((kk2 * 16 + (lane & 15)) * VSTR
                               + vt * 16 + (lane >> 4) * 8) * 2;
                ldsm_x4_t(Vh[0], Vh[1], Vh[2], Vh[3], sbase + OVH + voff);
                ldsm_x4_t(Vl[0], Vl[1], Vl[2], Vl[3], sbase + OVL + voff);
                #pragma unroll
                for (int mi = 0; mi < 2; ++mi) {
                    mma16816(o[mi][2 * vt + 0], Ph[mi], Vh[0], Vh[1]);
                    mma16816(o[mi][2 * vt + 1], Ph[mi], Vh[2], Vh[3]);
                    mma16816(o[mi][2 * vt + 0], Ph[mi], Vl[0], Vl[1]);
                    mma16816(o[mi][2 * vt + 1], Ph[mi], Vl[2], Vl[3]);
                    mma16816(o[mi][2 * vt + 0], Pl[mi], Vh[0], Vh[1]);
                    mma16816(o[mi][2 * vt + 1], Pl[mi], Vh[2], Vh[3]);
                }
            }
        }
        __syncthreads();
    }

    // ---- finalize: reduce row sums across the quad, scale, store ----
    #pragma unroll
    for (int i = 0; i < 4; ++i) {
        rs[i] += __shfl_xor_sync(0xFFFFFFFFu, rs[i], 1);
        rs[i] += __shfl_xor_sync(0xFFFFFFFFu, rs[i], 2);
        rs[i] = 1.0f / rs[i];
    }

    float* op = attn_out + (size_t)(b * NCTX) * DM + h * HD;
    #pragma unroll
    for (int mi = 0; mi < 2; ++mi)
        #pragma unroll
        for (int half = 0; half < 2; ++half) {
            const int row = q0 + wq0 + mi * 16 + g + half * 8;
            const float inv = rs[mi * 2 + half];
            #pragma unroll
            for (int nt = 0; nt < 9; ++nt) {
                const int col = nt * 8 + 2 * t;
                float2 v;
                v.x = o[mi][nt][half * 2 + 0] * inv;
                v.y = o[mi][nt][half * 2 + 1] * inv;
                *(float2*)(op + (size_t)row * DM + col) = v;
            }
        }
}

// ---------------------------------------------------------------------------
// Launch
// ---------------------------------------------------------------------------
extern "C" void kernel_launch(void* const* d_in, const int* in_sizes, int n_in,
                              void* d_out, int out_size)
{
    (void)in_sizes; (void)n_in; (void)out_size;
    const float* x    = (const float*)d_in[0];
    const float* cond = (const float*)d_in[1];
    const int*   mask = (const int*)  d_in[2];
    const float* wq   = (const float*)d_in[3];
    const float* bq   = (const float*)d_in[4];
    const float* wkv  = (const float*)d_in[5];
    const float* bkv  = (const float*)d_in[6];
    const float* wp   = (const float*)d_in[7];
    const float* bp   = (const float*)d_in[8];
    float* out        = (float*)d_out;

    float *qptr = nullptr, *attnptr = nullptr;
    cudaGetSymbolAddress((void**)&qptr,    g_q);
    cudaGetSymbolAddress((void**)&attnptr, g_attn);

    cudaFuncSetAttribute(gemm_hmma<0>,
                         cudaFuncAttributeMaxDynamicSharedMemorySize, GEMM_SMEM);
    cudaFuncSetAttribute(gemm_hmma<1>,
                         cudaFuncAttributeMaxDynamicSharedMemorySize, GEMM_SMEM);
    cudaFuncSetAttribute(attn_tc,
                         cudaFuncAttributeMaxDynamicSharedMemorySize, ATTN_SMEM);

    const int rowsA  = BSZ * NCTX;   // 32768
    const int rowsKV = BSZ * MCTX;   // 2400

    // 1) KV projection + transposed scatter
    {
        dim3 grid(2 * DM / 128, (rowsKV + 255) / 256);   // 18 x 10
        gemm_hmma<1><<<grid, 256, GEMM_SMEM>>>(cond, wkv, bkv, nullptr,
                                               rowsKV, 2 * DM, DM);
    }
    // 2) Q projection
    {
        dim3 grid(DM / 128, rowsA / 256);                // 9 x 128
        gemm_hmma<0><<<grid, 256, GEMM_SMEM>>>(x, wq, bq, qptr, rowsA, DM, DM);
    }
    // 3) Attention (tensor cores)
    {
        dim3 grid(NCTX / QR, NH, BSZ);                   // 32 x 16 x 8
        attn_tc<<<grid, 128, ATTN_SMEM>>>(mask, attnptr);
    }
    // 4) Output projection
    {
        dim3 grid(DM / 128, rowsA / 256);
        gemm_hmma<0><<<grid, 256, GEMM_SMEM>>>(attnptr, wp, bp, out, rowsA, DM, DM);
    }
}

// round 11
// speedup vs baseline: 1.2461x; 1.2461x over previous
#include <cuda_runtime.h>
#include <cuda_bf16.h>
#include <cstdint>

// ---------------------------------------------------------------------------
// Problem constants
// ---------------------------------------------------------------------------
constexpr int BSZ  = 8;
constexpr int NCTX = 4096;
constexpr int MCTX = 300;
constexpr int DM   = 1152;
constexpr int NH   = 16;
constexpr int HD   = 72;           // DM / NH
constexpr int MP   = 320;          // padded M for K^T / V scratch

// ---------------------------------------------------------------------------
// Scratch (device globals; zero-initialized, no allocations allowed)
// ---------------------------------------------------------------------------
__device__ float g_q   [(size_t)BSZ * NCTX * DM];          // [B,N,DM]
__device__ float g_attn[(size_t)BSZ * NCTX * DM];          // [B,N,DM]
__device__ float g_kT  [(size_t)BSZ * NH * HD * MP];       // [B,H,D,Mpad] (pads stay 0)
__device__ float g_v2  [(size_t)BSZ * NH * MP * 80];       // [B,H,Mpad,80] (pads stay 0)

// ---------------------------------------------------------------------------
// Helpers
// ---------------------------------------------------------------------------
__device__ __forceinline__ uint32_t smem_u32(const void* p) {
    uint32_t a;
    asm("{ .reg .u64 t; cvta.to.shared.u64 t, %1; cvt.u32.u64 %0, t; }"
        : "=r"(a) : "l"(p));
    return a;
}

__device__ __forceinline__ uint32_t pack_bf2(__nv_bfloat16 a, __nv_bfloat16 b) {
    __nv_bfloat162 t(a, b);
    return *reinterpret_cast<uint32_t*>(&t);
}

__device__ __forceinline__ void split_bf16(float v, __nv_bfloat16& h, __nv_bfloat16& l) {
    h = __float2bfloat16_rn(v);
    l = __float2bfloat16_rn(v - __bfloat162float(h));
}

__device__ __forceinline__ void ldsm_x4(uint32_t& r0, uint32_t& r1,
                                        uint32_t& r2, uint32_t& r3, uint32_t a) {
    asm volatile("ldmatrix.sync.aligned.m8n8.x4.shared.b16 {%0,%1,%2,%3}, [%4];"
                 : "=r"(r0), "=r"(r1), "=r"(r2), "=r"(r3) : "r"(a));
}

__device__ __forceinline__ void ldsm_x4_t(uint32_t& r0, uint32_t& r1,
                                          uint32_t& r2, uint32_t& r3, uint32_t a) {
    asm volatile("ldmatrix.sync.aligned.m8n8.x4.trans.shared.b16 {%0,%1,%2,%3}, [%4];"
                 : "=r"(r0), "=r"(r1), "=r"(r2), "=r"(r3) : "r"(a));
}

__device__ __forceinline__ void mma16816(float* d, const uint32_t* a,
                                         uint32_t b0, uint32_t b1) {
    asm volatile(
        "mma.sync.aligned.m16n8k16.row.col.f32.bf16.bf16.f32 "
        "{%0,%1,%2,%3}, {%4,%5,%6,%7}, {%8,%9}, {%0,%1,%2,%3};"
        : "+f"(d[0]), "+f"(d[1]), "+f"(d[2]), "+f"(d[3])
        : "r"(a[0]), "r"(a[1]), "r"(a[2]), "r"(a[3]), "r"(b0), "r"(b1));
}

// ---------------------------------------------------------------------------
// HMMA split-bf16 GEMM: C[Mr,Nc] = A[Mr,Kd] @ B[Kd,Nc] + bias
// CTA tile 128x128, BK=32, 4 warps (2x2 of 64x64), 128 threads, occ 2.
// Double-buffered SMEM; next-chunk A operand prefetched in registers.
// MODE 0: row-major store. MODE 1: KV scatter into g_kT / g_v2.
// ---------------------------------------------------------------------------
constexpr int AS_STRIDE = 40;    // 32 + 8 pad (elems)
constexpr int BS_STRIDE = 136;   // 128 + 8 pad (elems)
constexpr int A_TILE_B  = 128 * AS_STRIDE * 2;   // 10240
constexpr int B_TILE_B  = 32  * BS_STRIDE * 2;   // 8704
constexpr int OFF_AH = 0;
constexpr int OFF_AL = OFF_AH + A_TILE_B;        // 10240
constexpr int OFF_BH = OFF_AL + A_TILE_B;        // 20480
constexpr int OFF_BL = OFF_BH + B_TILE_B;        // 29184
constexpr int STAGE_B = OFF_BL + B_TILE_B;       // 37888
constexpr int GEMM_SMEM = 2 * STAGE_B;           // 75776

template <int MODE>
__global__ __launch_bounds__(128, 2)
void gemm_hmma(const float* __restrict__ A, const float* __restrict__ Bm,
               const float* __restrict__ bias, float* __restrict__ C,
               int Mr, int Nc, int Kd)
{
    extern __shared__ char dsm[];
    const uint32_t sbase = smem_u32(dsm);

    const int tid  = threadIdx.x;
    const int wid  = tid >> 5;
    const int lane = tid & 31;
    const int n0   = blockIdx.x * 128;
    const int m0   = blockIdx.y * 128;
    const int wm   = wid >> 1;          // 0..1
    const int wn   = wid & 1;           // 0..1

    // producer mappings (coalesced)
    const int arBase = tid >> 3;        // A: 16 rows per pass, 8 passes
    const int acol   = (tid & 7) * 4;
    const int bcol   = lane * 4;        // B: warp per row, 8 passes

    // consumer lane addressing
    const int aFragRow = wm * 64 + (lane & 15);
    const int aFragCol = (lane >> 4) * 8;
    const int bFragRow = lane & 15;
    const int bFragCol = wn * 64 + (lane >> 4) * 8;

    float acc[4][8][4];
    #pragma unroll
    for (int i = 0; i < 4; i++)
        #pragma unroll
        for (int j = 0; j < 8; j++)
            #pragma unroll
            for (int e = 0; e < 4; e++) acc[i][j][e] = 0.0f;

    const int nchunks = Kd / 32;

    // ---- produce chunk 0 into stage 0 ----
    {
        char* pAH = dsm + OFF_AH;
        char* pAL = dsm + OFF_AL;
        char* pBH = dsm + OFF_BH;
        char* pBL = dsm + OFF_BL;
        #pragma unroll
        for (int it = 0; it < 8; ++it) {
            const int r = arBase + it * 16;
            int arow = m0 + r; if (arow >= Mr) arow = Mr - 1;
            float4 v = *(const float4*)(A + (size_t)arow * Kd + acol);
            __nv_bfloat16 h0, h1, h2, h3, l0, l1, l2, l3;
            split_bf16(v.x, h0, l0); split_bf16(v.y, h1, l1);
            split_bf16(v.z, h2, l2); split_bf16(v.w, h3, l3);
            const uint32_t off = (uint32_t)(r * AS_STRIDE + acol) * 2;
            *(uint2*)(pAH + off) = make_uint2(pack_bf2(h0, h1), pack_bf2(h2, h3));
            *(uint2*)(pAL + off) = make_uint2(pack_bf2(l0, l1), pack_bf2(l2, l3));
        }
        #pragma unroll
        for (int it = 0; it < 8; ++it) {
            const int r = wid + it * 4;
            float4 v = *(const float4*)(Bm + (size_t)r * Nc + n0 + bcol);
            __nv_bfloat16 h0, h1, h2, h3, l0, l1, l2, l3;
            split_bf16(v.x, h0, l0); split_bf16(v.y, h1, l1);
            split_bf16(v.z, h2, l2); split_bf16(v.w, h3, l3);
            const uint32_t off = (uint32_t)(r * BS_STRIDE + bcol) * 2;
            *(uint2*)(pBH + off) = make_uint2(pack_bf2(h0, h1), pack_bf2(h2, h3));
            *(uint2*)(pBL + off) = make_uint2(pack_bf2(l0, l1), pack_bf2(l2, l3));
        }
    }
    __syncthreads();

    for (int c = 0; c < nchunks; ++c) {
        const int cur = c & 1;
        const int nb  = c + 1;
        const bool havenb = nb < nchunks;

        // ---- prefetch next A chunk into registers (latency hides under MMA) ----
        float4 pa[8];
        if (havenb) {
            const int k0n = nb * 32;
            #pragma unroll
            for (int it = 0; it < 8; ++it) {
                const int r = arBase + it * 16;
                int arow = m0 + r; if (arow >= Mr) arow = Mr - 1;
                pa[it] = *(const float4*)(A + (size_t)arow * Kd + k0n + acol);
            }
        }

        // ---- MMA on stage cur ----
        const uint32_t sAH = sbase + cur * STAGE_B + OFF_AH;
        const uint32_t sAL = sbase + cur * STAGE_B + OFF_AL;
        const uint32_t sBH = sbase + cur * STAGE_B + OFF_BH;
        const uint32_t sBL = sbase + cur * STAGE_B + OFF_BL;

        #pragma unroll
        for (int kk = 0; kk < 32; kk += 16) {
            uint32_t Ah[4][4], Bh[4][4];
            #pragma unroll
            for (int mi = 0; mi < 4; ++mi) {
                uint32_t a = sAH + (uint32_t)((aFragRow + mi * 16) * AS_STRIDE
                                              + kk + aFragCol) * 2;
                ldsm_x4(Ah[mi][0], Ah[mi][1], Ah[mi][2], Ah[mi][3], a);
            }
            #pragma unroll
            for (int nj = 0; nj < 4; ++nj) {
                uint32_t boff = (uint32_t)((kk + bFragRow) * BS_STRIDE
                                           + bFragCol + nj * 16) * 2;
                ldsm_x4_t(Bh[nj][0], Bh[nj][1], Bh[nj][2], Bh[nj][3], sBH + boff);
            }
            // passes 1+2 in halves to limit live Bl registers
            #pragma unroll
            for (int half = 0; half < 2; ++half) {
                uint32_t Bl[2][4];
                #pragma unroll
                for (int j = 0; j < 2; ++j) {
                    const int nj = half * 2 + j;
                    uint32_t boff = (uint32_t)((kk + bFragRow) * BS_STRIDE
                                               + bFragCol + nj * 16) * 2;
                    ldsm_x4_t(Bl[j][0], Bl[j][1], Bl[j][2], Bl[j][3], sBL + boff);
                }
                #pragma unroll
                for (int mi = 0; mi < 4; ++mi)
                    #pragma unroll
                    for (int f = 0; f < 4; ++f) {
                        const int nf = half * 4 + f;
                        const int nj = nf >> 1, sub = (nf & 1) * 2;
                        mma16816(acc[mi][nf], Ah[mi], Bh[nj][sub], Bh[nj][sub + 1]);
                        mma16816(acc[mi][nf], Ah[mi], Bl[f >> 1][sub], Bl[f >> 1][sub + 1]);
                    }
            }
            // pass 3: Al * Bh
            uint32_t Al[4][4];
            #pragma unroll
            for (int mi = 0; mi < 4; ++mi) {
                uint32_t a = sAL + (uint32_t)((aFragRow + mi * 16) * AS_STRIDE
                                              + kk + aFragCol) * 2;
                ldsm_x4(Al[mi][0], Al[mi][1], Al[mi][2], Al[mi][3], a);
            }
            #pragma unroll
            for (int mi = 0; mi < 4; ++mi)
                #pragma unroll
                for (int nf = 0; nf < 8; ++nf) {
                    const int nj = nf >> 1, sub = (nf & 1) * 2;
                    mma16816(acc[mi][nf], Al[mi], Bh[nj][sub], Bh[nj][sub + 1]);
                }
        }

        // ---- store prefetched A, produce next B, into stage nb&1 ----
        if (havenb) {
            char* pAH = dsm + (nb & 1) * STAGE_B + OFF_AH;
            char* pAL = dsm + (nb & 1) * STAGE_B + OFF_AL;
            char* pBH = dsm + (nb & 1) * STAGE_B + OFF_BH;
            char* pBL = dsm + (nb & 1) * STAGE_B + OFF_BL;
            #pragma unroll
            for (int it = 0; it < 8; ++it) {
                const int r = arBase + it * 16;
                float4 v = pa[it];
                __nv_bfloat16 h0, h1, h2, h3, l0, l1, l2, l3;
                split_bf16(v.x, h0, l0); split_bf16(v.y, h1, l1);
                split_bf16(v.z, h2, l2); split_bf16(v.w, h3, l3);
                const uint32_t off = (uint32_t)(r * AS_STRIDE + acol) * 2;
                *(uint2*)(pAH + off) = make_uint2(pack_bf2(h0, h1), pack_bf2(h2, h3));
                *(uint2*)(pAL + off) = make_uint2(pack_bf2(l0, l1), pack_bf2(l2, l3));
            }
            const int k0n = nb * 32;
            #pragma unroll
            for (int it = 0; it < 8; ++it) {
                const int r = wid + it * 4;
                float4 v = *(const float4*)(Bm + (size_t)(k0n + r) * Nc + n0 + bcol);
                __nv_bfloat16 h0, h1, h2, h3, l0, l1, l2, l3;
                split_bf16(v.x, h0, l0); split_bf16(v.y, h1, l1);
                split_bf16(v.z, h2, l2); split_bf16(v.w, h3, l3);
                const uint32_t off = (uint32_t)(r * BS_STRIDE + bcol) * 2;
                *(uint2*)(pBH + off) = make_uint2(pack_bf2(h0, h1), pack_bf2(h2, h3));
                *(uint2*)(pBL + off) = make_uint2(pack_bf2(l0, l1), pack_bf2(l2, l3));
            }
        }
        __syncthreads();
    }

    // ---------------- epilogue ----------------
    const int g = lane >> 2;
    const int t = lane & 3;
    #pragma unroll
    for (int mi = 0; mi < 4; ++mi) {
        #pragma unroll
        for (int half = 0; half < 2; ++half) {
            const int row = m0 + wm * 64 + mi * 16 + g + half * 8;
            if (row >= Mr) continue;
            #pragma unroll
            for (int nf = 0; nf < 8; ++nf) {
                const int col = n0 + wn * 64 + nf * 8 + 2 * t;
                float v0 = acc[mi][nf][half * 2 + 0] + bias[col];
                float v1 = acc[mi][nf][half * 2 + 1] + bias[col + 1];
                if (MODE == 0) {
                    *(float2*)(C + (size_t)row * Nc + col) = make_float2(v0, v1);
                } else {
                    const int b = row / MCTX, m = row - b * MCTX;
                    #pragma unroll
                    for (int e = 0; e < 2; ++e) {
                        int c2 = col + e;
                        const float val = e ? v1 : v0;
                        if (c2 < DM) {   // K: transposed [b,h,d,m]
                            const int h = c2 / HD, d = c2 - h * HD;
                            g_kT[((size_t)(b * NH + h) * HD + d) * MP + m] = val;
                        } else {         // V: [b,h,m,80]
                            c2 -= DM;
                            const int h = c2 / HD, d = c2 - h * HD;
                            g_v2[((size_t)(b * NH + h) * MP + m) * 80 + d] = val;
                        }
                    }
                }
            }
        }
    }
}

// ---------------------------------------------------------------------------
// Tensor-core attention (flash-style, no max subtraction — scores are O(1)).
// CTA = (b, h, 128 q-rows); 4 warps x 32 q-rows; stream M in chunks of 64.
// Split-3 bf16 on both QK^T and P@V; O and row-sums accumulate un-rescaled.
// ---------------------------------------------------------------------------
constexpr int QR   = 128;
constexpr int MC   = 64;
constexpr int DP   = 80;    // padded head dim
constexpr int QSTR = 88;    // smem strides (elems), 16B-aligned rows
constexpr int KSTR = 72;
constexpr int VSTR = 88;
constexpr int OQH = 0;
constexpr int OQL = OQH + QR * QSTR * 2;     // 22528
constexpr int OKH = OQL + QR * QSTR * 2;     // 45056
constexpr int OKL = OKH + DP * KSTR * 2;     // 56576
constexpr int OVH = OKL + DP * KSTR * 2;     // 68096
constexpr int OVL = OVH + MC * VSTR * 2;     // 79360
constexpr int ATTN_SMEM = OVL + MC * VSTR * 2; // 90624

__global__ __launch_bounds__(128, 2)
void attn_tc(const int* __restrict__ mask, float* __restrict__ attn_out)
{
    extern __shared__ char dsm[];
    const uint32_t sbase = smem_u32(dsm);

    const int b   = blockIdx.z;
    const int h   = blockIdx.y;
    const int q0  = blockIdx.x * QR;
    const int tid = threadIdx.x;
    const int wid = tid >> 5;
    const int lane = tid & 31;
    const int g   = lane >> 2;
    const int t   = lane & 3;
    const int wq0 = wid * 32;
    const int mv  = mask[b];

    const float scale = rsqrtf((float)HD);

    // ---- produce Q tile (128 x 80; cols 72..79 zero), scale folded in ----
    {
        char* pQH = dsm + OQH;
        char* pQL = dsm + OQL;
        const float* qg = g_q + ((size_t)(b * NCTX) + q0) * DM + h * HD;
        for (int task = tid; task < QR * 18; task += 128) {
            const int r = task / 18, f4 = task - r * 18;
            float4 v = *(const float4*)(qg + (size_t)r * DM + f4 * 4);
            v.x *= scale; v.y *= scale; v.z *= scale; v.w *= scale;
            __nv_bfloat16 h0, h1, h2, h3, l0, l1, l2, l3;
            split_bf16(v.x, h0, l0); split_bf16(v.y, h1, l1);
            split_bf16(v.z, h2, l2); split_bf16(v.w, h3, l3);
            const uint32_t off = (uint32_t)(r * QSTR + f4 * 4) * 2;
            *(uint2*)(pQH + off) = make_uint2(pack_bf2(h0, h1), pack_bf2(h2, h3));
            *(uint2*)(pQL + off) = make_uint2(pack_bf2(l0, l1), pack_bf2(l2, l3));
        }
        for (int task = tid; task < QR * 2; task += 128) {
            const int r = task >> 1, f4 = 18 + (task & 1);
            const uint32_t off = (uint32_t)(r * QSTR + f4 * 4) * 2;
            *(uint2*)(pQH + off) = make_uint2(0u, 0u);
            *(uint2*)(pQL + off) = make_uint2(0u, 0u);
        }
    }

    float o[2][10][4];
    #pragma unroll
    for (int i = 0; i < 2; i++)
        #pragma unroll
        for (int j = 0; j < 10; j++)
            #pragma unroll
            for (int e = 0; e < 4; e++) o[i][j][e] = 0.0f;
    float rs[4] = {0.f, 0.f, 0.f, 0.f};

    for (int c0 = 0; c0 < mv; c0 += MC) {
        // ---- produce K^T tile (80 d-rows x 64 m-cols; rows 72..79 zero) ----
        {
            char* pKH = dsm + OKH;
            char* pKL = dsm + OKL;
            const float* kg = g_kT + (size_t)(b * NH + h) * HD * MP + c0;
            for (int task = tid; task < HD * 16; task += 128) {
                const int d = task >> 4, f4 = task & 15;
                float4 v = *(const float4*)(kg + (size_t)d * MP + f4 * 4);
                __nv_bfloat16 h0, h1, h2, h3, l0, l1, l2, l3;
                split_bf16(v.x, h0, l0); split_bf16(v.y, h1, l1);
                split_bf16(v.z, h2, l2); split_bf16(v.w, h3, l3);
                const uint32_t off = (uint32_t)(d * KSTR + f4 * 4) * 2;
                *(uint2*)(pKH + off) = make_uint2(pack_bf2(h0, h1), pack_bf2(h2, h3));
                *(uint2*)(pKL + off) = make_uint2(pack_bf2(l0, l1), pack_bf2(l2, l3));
            }
            for (int task = tid; task < 8 * 16; task += 128) {
                const int d = HD + (task >> 4), f4 = task & 15;
                const uint32_t off = (uint32_t)(d * KSTR + f4 * 4) * 2;
                *(uint2*)(pKH + off) = make_uint2(0u, 0u);
                *(uint2*)(pKL + off) = make_uint2(0u, 0u);
            }
        }
        // ---- produce V tile (64 m-rows x 80 d-cols) ----
        {
            char* pVH = dsm + OVH;
            char* pVL = dsm + OVL;
            const float* vg = g_v2 + ((size_t)(b * NH + h) * MP + c0) * 80;
            for (int task = tid; task < MC * 20; task += 128) {
                const int m = task / 20, f4 = task - m * 20;
                float4 v = *(const float4*)(vg + (size_t)m * 80 + f4 * 4);
                __nv_bfloat16 h0, h1, h2, h3, l0, l1, l2, l3;
                split_bf16(v.x, h0, l0); split_bf16(v.y, h1, l1);
                split_bf16(v.z, h2, l2); split_bf16(v.w, h3, l3);
                const uint32_t off = (uint32_t)(m * VSTR + f4 * 4) * 2;
                *(uint2*)(pVH + off) = make_uint2(pack_bf2(h0, h1), pack_bf2(h2, h3));
                *(uint2*)(pVL + off) = make_uint2(pack_bf2(l0, l1), pack_bf2(l2, l3));
            }
        }
        __syncthreads();

        // ---- S = Q @ K^T (split-3) ----
        float S[2][8][4];
        #pragma unroll
        for (int i = 0; i < 2; i++)
            #pragma unroll
            for (int j = 0; j < 8; j++)
                #pragma unroll
                for (int e = 0; e < 4; e++) S[i][j][e] = 0.0f;

        #pragma unroll
        for (int kk = 0; kk < 5; ++kk) {
            uint32_t Ah[2][4], Al[2][4];
            #pragma unroll
            for (int mi = 0; mi < 2; ++mi) {
                const uint32_t aoff =
                    (uint32_t)((wq0 + mi * 16 + (lane & 15)) * QSTR
                               + kk * 16 + (lane >> 4) * 8) * 2;
                ldsm_x4(Ah[mi][0], Ah[mi][1], Ah[mi][2], Ah[mi][3], sbase + OQH + aoff);
                ldsm_x4(Al[mi][0], Al[mi][1], Al[mi][2], Al[mi][3], sbase + OQL + aoff);
            }
            #pragma unroll
            for (int nj = 0; nj < 4; ++nj) {
                uint32_t Bh[4], Bl[4];
                const uint32_t boff =
                    (uint32_t)((kk * 16 + (lane & 15)) * KSTR
                               + nj * 16 + (lane >> 4) * 8) * 2;
                ldsm_x4_t(Bh[0], Bh[1], Bh[2], Bh[3], sbase + OKH + boff);
                ldsm_x4_t(Bl[0], Bl[1], Bl[2], Bl[3], sbase + OKL + boff);
                #pragma unroll
                for (int mi = 0; mi < 2; ++mi) {
                    mma16816(S[mi][2 * nj + 0], Ah[mi], Bh[0], Bh[1]);
                    mma16816(S[mi][2 * nj + 1], Ah[mi], Bh[2], Bh[3]);
                    mma16816(S[mi][2 * nj + 0], Ah[mi], Bl[0], Bl[1]);
                    mma16816(S[mi][2 * nj + 1], Ah[mi], Bl[2], Bl[3]);
                    mma16816(S[mi][2 * nj + 0], Al[mi], Bh[0], Bh[1]);
                    mma16816(S[mi][2 * nj + 1], Al[mi], Bh[2], Bh[3]);
                }
            }
        }

        // ---- softmax numerators p = exp(s); accumulate row sums ----
        if (c0 + MC <= mv) {
            // full chunk: no mask predication
            #pragma unroll
            for (int mi = 0; mi < 2; ++mi)
                #pragma unroll
                for (int nf = 0; nf < 8; ++nf)
                    #pragma unroll
                    for (int e = 0; e < 4; ++e) {
                        const float p = __expf(S[mi][nf][e]);
                        S[mi][nf][e] = p;
                        rs[mi * 2 + (e >> 1)] += p;
                    }
        } else {
            #pragma unroll
            for (int mi = 0; mi < 2; ++mi)
                #pragma unroll
                for (int nf = 0; nf < 8; ++nf)
                    #pragma unroll
                    for (int e = 0; e < 4; ++e) {
                        const int col = c0 + nf * 8 + 2 * t + (e & 1);
                        const float p = (col < mv) ? __expf(S[mi][nf][e]) : 0.0f;
                        S[mi][nf][e] = p;
                        rs[mi * 2 + (e >> 1)] += p;
                    }
        }

        // ---- O += P @ V (split-3) ----
        #pragma unroll
        for (int kk2 = 0; kk2 < 4; ++kk2) {
            uint32_t Ph[2][4], Pl[2][4];
            #pragma unroll
            for (int mi = 0; mi < 2; ++mi) {
                const int nfa = 2 * kk2, nfb = nfa + 1;
                __nv_bfloat16 hh, ll;
                uint32_t hp[8], lp[8];
                #pragma unroll
                for (int e = 0; e < 4; ++e) {
                    split_bf16(S[mi][nfa][e], hh, ll);
                    hp[e] = (uint32_t)*(uint16_t*)&hh;
                    lp[e] = (uint32_t)*(uint16_t*)&ll;
                    split_bf16(S[mi][nfb][e], hh, ll);
                    hp[4 + e] = (uint32_t)*(uint16_t*)&hh;
                    lp[4 + e] = (uint32_t)*(uint16_t*)&ll;
                }
                Ph[mi][0] = hp[0] | (hp[1] << 16);
                Ph[mi][1] = hp[2] | (hp[3] << 16);
                Ph[mi][2] = hp[4] | (hp[5] << 16);
                Ph[mi][3] = hp[6] | (hp[7] << 16);
                Pl[mi][0] = lp[0] | (lp[1] << 16);
                Pl[mi][1] = lp[2] | (lp[3] << 16);
                Pl[mi][2] = lp[4] | (lp[5] << 16);
                Pl[mi][3] = lp[6] | (lp[7] << 16);
            }
            #pragma unroll
            for (int vt = 0; vt < 5; ++vt) {
                uint32_t Vh[4], Vl[4];
                const uint32_t voff =
                    (uint32_t)((kk2 * 16 + (lane & 15)) * VSTR
                               + vt * 16 + (lane >> 4) * 8) * 2;
                ldsm_x4_t(Vh[0], Vh[1], Vh[2], Vh[3], sbase + OVH + voff);
                ldsm_x4_t(Vl[0], Vl[1], Vl[2], Vl[3], sbase + OVL + voff);
                #pragma unroll
                for (int mi = 0; mi < 2; ++mi) {
                    mma16816(o[mi][2 * vt + 0], Ph[mi], Vh[0], Vh[1]);
                    mma16816(o[mi][2 * vt + 1], Ph[mi], Vh[2], Vh[3]);
                    mma16816(o[mi][2 * vt + 0], Ph[mi], Vl[0], Vl[1]);
                    mma16816(o[mi][2 * vt + 1], Ph[mi], Vl[2], Vl[3]);
                    mma16816(o[mi][2 * vt + 0], Pl[mi], Vh[0], Vh[1]);
                    mma16816(o[mi][2 * vt + 1], Pl[mi], Vh[2], Vh[3]);
                }
            }
        }
        __syncthreads();
    }

    // ---- finalize: reduce row sums across the quad, scale, store ----
    #pragma unroll
    for (int i = 0; i < 4; ++i) {
        rs[i] += __shfl_xor_sync(0xFFFFFFFFu, rs[i], 1);
        rs[i] += __shfl_xor_sync(0xFFFFFFFFu, rs[i], 2);
        rs[i] = 1.0f / rs[i];
    }

    float* op = attn_out + (size_t)(b * NCTX) * DM + h * HD;
    #pragma unroll
    for (int mi = 0; mi < 2; ++mi)
        #pragma unroll
        for (int half = 0; half < 2; ++half) {
            const int row = q0 + wq0 + mi * 16 + g + half * 8;
            const float inv = rs[mi * 2 + half];
            #pragma unroll
            for (int nt = 0; nt < 9; ++nt) {
                const int col = nt * 8 + 2 * t;
                float2 v;
                v.x = o[mi][nt][half * 2 + 0] * inv;
                v.y = o[mi][nt][half * 2 + 1] * inv;
                *(float2*)(op + (size_t)row * DM + col) = v;
            }
        }
}

// ---------------------------------------------------------------------------
// Launch
// ---------------------------------------------------------------------------
extern "C" void kernel_launch(void* const* d_in, const int* in_sizes, int n_in,
                              void* d_out, int out_size)
{
    (void)in_sizes; (void)n_in; (void)out_size;
    const float* x    = (const float*)d_in[0];
    const float* cond = (const float*)d_in[1];
    const int*   mask = (const int*)  d_in[2];
    const float* wq   = (const float*)d_in[3];
    const float* bq   = (const float*)d_in[4];
    const float* wkv  = (const float*)d_in[5];
    const float* bkv  = (const float*)d_in[6];
    const float* wp   = (const float*)d_in[7];
    const float* bp   = (const float*)d_in[8];
    float* out        = (float*)d_out;

    float *qptr = nullptr, *attnptr = nullptr;
    cudaGetSymbolAddress((void**)&qptr,    g_q);
    cudaGetSymbolAddress((void**)&attnptr, g_attn);

    cudaFuncSetAttribute(gemm_hmma<0>,
                         cudaFuncAttributeMaxDynamicSharedMemorySize, GEMM_SMEM);
    cudaFuncSetAttribute(gemm_hmma<1>,
                         cudaFuncAttributeMaxDynamicSharedMemorySize, GEMM_SMEM);
    cudaFuncSetAttribute(attn_tc,
                         cudaFuncAttributeMaxDynamicSharedMemorySize, ATTN_SMEM);

    const int rowsA  = BSZ * NCTX;   // 32768
    const int rowsKV = BSZ * MCTX;   // 2400

    // 1) KV projection + transposed scatter
    {
        dim3 grid(2 * DM / 128, (rowsKV + 127) / 128);   // 18 x 19
        gemm_hmma<1><<<grid, 128, GEMM_SMEM>>>(cond, wkv, bkv, nullptr,
                                               rowsKV, 2 * DM, DM);
    }
    // 2) Q projection
    {
        dim3 grid(DM / 128, rowsA / 128);                // 9 x 256
        gemm_hmma<0><<<grid, 128, GEMM_SMEM>>>(x, wq, bq, qptr, rowsA, DM, DM);
    }
    // 3) Attention (tensor cores)
    {
        dim3 grid(NCTX / QR, NH, BSZ);                   // 32 x 16 x 8
        attn_tc<<<grid, 128, ATTN_SMEM>>>(mask, attnptr);
    }
    // 4) Output projection
    {
        dim3 grid(DM / 128, rowsA / 128);
        gemm_hmma<0><<<grid, 128, GEMM_SMEM>>>(attnptr, wp, bp, out, rowsA, DM, DM);
    }
}